// round 2
// baseline (speedup 1.0000x reference)
#include <cuda_runtime.h>

#define NB 16384

enum { L_E1 = 0, L_E2, L_E3, L_E4, L_D1, L_D2, L_D3, L_D4 };

// Output layout (concatenated flat outputs, float32):
//   zq3   : [0, 8388608)            (N,512,1)
//   x_hat : [8388608, 50331648)     (N,256,10)
//   idx   : [50331648, 50348032)    (N,1) as float
//   emb_loss, qq_loss, ac_loss : 3 scalars
#define ZQ_OFF   0
#define XHAT_OFF 8388608
#define IDX_OFF  50331648
#define EMB_OFF  50348032

// ---- scratch (device globals; no allocation allowed) ----
__device__ float g_h1[NB * 1280];   // (N,10,128) encoder conv1 out (post-relu)
__device__ float g_h2[NB * 1024];   // (N,4,256)  encoder conv2 out (post-relu)
__device__ float g_h3[NB * 512];    // (N,512)    encoder conv3 out (post-relu)
__device__ float g_z [NB * 512];    // (N,512)    z_e
__device__ float g_zn[NB];          // |z|^2 per row, correctly-rounded fp32
__device__ float g_d1[NB * 512];    // (N,512)    decoder convT1 out (post-relu)
__device__ float g_d2[NB * 1024];   // (N, s(4), i(256)) decoder convT2 out (post-relu)
__device__ float g_y [NB * 1280];   // (N, o(128), t(10)) convT3 accumulator (pre-relu)
__device__ int   g_idx[NB];

// transformed weights: uniform [K][N] layout
__device__ float g_W1t[256 * 128];
__device__ float g_W2t[512 * 256];
__device__ float g_W3t[1024 * 512];
__device__ float g_W4t[512 * 512];
__device__ float g_V2t[512 * 1024];
__device__ float g_CBt[512 * 1024]; // codebook transposed (k, e)
__device__ float g_cbn[1024];       // |e|^2 (fp64-accumulated, rounded to fp32)
__device__ double g_loss;

// ---------------------------------------------------------------------------
// weight pre-transforms (cheap, a few MB, run every launch)
// ---------------------------------------------------------------------------
__global__ void prep_kernel(const float* __restrict__ ew1, const float* __restrict__ ew2,
                            const float* __restrict__ ew3, const float* __restrict__ ew4,
                            const float* __restrict__ cb,  const float* __restrict__ dw2)
{
    int e = blockIdx.x * blockDim.x + threadIdx.x;   // 524288 threads
    if (e < 256 * 128)  { int k = e >> 7,  o = e & 127;  g_W1t[e] = ew1[o * 256 + k]; }
    if (e < 512 * 256)  { int k = e >> 8,  o = e & 255;  g_W2t[e] = ew2[o * 512 + (k & 127) * 4 + (k >> 7)]; }
    if (e < 1024 * 512) { int k = e >> 9,  o = e & 511;  g_W3t[e] = ew3[o * 1024 + (k & 255) * 4 + (k >> 8)]; }
    if (e < 512 * 512)  { int k = e >> 9,  o = e & 511;  g_W4t[e] = ew4[o * 512 + k]; }
    if (e < 512 * 1024) { int k = e >> 10, c = e & 1023; g_CBt[e] = cb[c * 512 + k]; }
    if (e < 512 * 1024) { int k = e >> 10, j = e & 1023; g_V2t[e] = dw2[k * 1024 + (j & 255) * 4 + (j >> 8)]; }
    if (e < 1024) {
        // |e|^2: fp32 elementwise square (as the reference does), fp64 sum, round once.
        double s = 0.0;
        for (int k = 0; k < 512; k++) { float v = cb[e * 512 + k]; s += (double)(v * v); }
        g_cbn[e] = (float)s;
    }
    if (e == 0) g_loss = 0.0;
}

// ---------------------------------------------------------------------------
// per-row |z|^2: fp32 squares, fp64 accumulate, single rounding to fp32
// ---------------------------------------------------------------------------
__global__ void rownorm_kernel()
{
    int warp = (blockIdx.x * blockDim.x + threadIdx.x) >> 5;  // one warp per row
    int lane = threadIdx.x & 31;
    if (warp >= NB) return;
    const float* zr = g_z + warp * 512;
    double s = 0.0;
    for (int k = lane; k < 512; k += 32) {
        float v = zr[k];
        s += (double)(v * v);
    }
#pragma unroll
    for (int o = 16; o > 0; o >>= 1)
        s += __shfl_down_sync(0xffffffffu, s, o);
    if (lane == 0) g_zn[warp] = (float)s;
}

// ---------------------------------------------------------------------------
// per-layer A-tile element loads (im2col folded in)
// ---------------------------------------------------------------------------
template <int L>
__device__ __forceinline__ float ldA(const float* __restrict__ A, int m, int k, int sarg)
{
    if constexpr (L == L_E1) {           // x (N,256,10), m = n*10+t
        int n = m / 10, t = m - n * 10;
        return A[n * 2560 + k * 10 + t];
    } else if constexpr (L == L_E2) {    // h1 (N,10,128), m = n*4+s, k = kk*128+i
        int n = m >> 2, s = m & 3;
        return A[(n * 10 + 2 * s + (k >> 7)) * 128 + (k & 127)];
    } else if constexpr (L == L_E3) {
        return A[m * 1024 + k];
    } else if constexpr (L == L_D3) {    // d2 (N, s, i): slice sarg
        return A[m * 1024 + sarg * 256 + k];
    } else if constexpr (L == L_D4) {    // y (N,o,t) with deferred relu, m = n*10+t, k = o
        int n = m / 10, t = m - n * 10;
        return fmaxf(A[n * 1280 + k * 10 + t], 0.0f);
    } else {                             // E4, D1, D2: (N,512)
        return A[m * 512 + k];
    }
}

// ---------------------------------------------------------------------------
// generic fp32 SGEMM: 128x128 block tile, 8x8 per thread, BK=16
// ---------------------------------------------------------------------------
template <int L>
__global__ __launch_bounds__(256, 2)
void gemm_k(const float* __restrict__ extA, const float* __restrict__ extB,
            const float* __restrict__ bias, float* __restrict__ extC, int sarg)
{
    constexpr int K  = (L == L_E1) ? 256 : (L == L_E2) ? 512 : (L == L_E3) ? 1024 :
                       (L == L_E4) ? 512 : (L == L_D1) ? 512 : (L == L_D2) ? 512 :
                       (L == L_D3) ? 256 : 128;
    constexpr int NT = (L == L_E1) ? 128 : (L == L_E2) ? 256 : (L == L_E3) ? 512 :
                       (L == L_E4) ? 512 : (L == L_D1) ? 512 : (L == L_D2) ? 1024 :
                       (L == L_D3) ? 512 : 256;
    constexpr bool MFAST = (L == L_E1 || L == L_D4);  // A contiguous-ish in m
    constexpr bool RELU  = (L == L_E1 || L == L_E2 || L == L_E3 || L == L_D1 || L == L_D2);

    const float* A = extA;
    const float* B = extB;
    float* C = extC;
    if constexpr (L == L_E1) { B = g_W1t; C = g_h1; }
    if constexpr (L == L_E2) { A = g_h1; B = g_W2t; C = g_h2; }
    if constexpr (L == L_E3) { A = g_h2; B = g_W3t; C = g_h3; }
    if constexpr (L == L_E4) { A = g_h3; B = g_W4t; C = g_z; }
    if constexpr (L == L_D1) { C = g_d1; }
    if constexpr (L == L_D2) { A = g_d1; B = g_V2t; C = g_d2; }
    if constexpr (L == L_D3) { A = g_d2; C = g_y; }
    if constexpr (L == L_D4) { A = g_y; }

    __shared__ float As[16][132];
    __shared__ float Bs[16][132];

    const int tid = threadIdx.x;
    const int m0 = blockIdx.y * 128;
    const int n0 = blockIdx.x * 128;
    const int tr = (tid >> 4) * 8;
    const int tc = (tid & 15) * 8;

    float acc[8][8];
#pragma unroll
    for (int i = 0; i < 8; i++)
#pragma unroll
        for (int j = 0; j < 8; j++) acc[i][j] = 0.0f;

    for (int k0 = 0; k0 < K; k0 += 16) {
        if constexpr (MFAST) {
#pragma unroll
            for (int i = 0; i < 8; i++) {
                int e = i * 256 + tid;
                int kl = e >> 7, ml = e & 127;
                As[kl][ml] = ldA<L>(A, m0 + ml, k0 + kl, sarg);
            }
        } else {
            int ml = tid >> 1, k8 = (tid & 1) * 8;
#pragma unroll
            for (int i = 0; i < 8; i++)
                As[k8 + i][ml] = ldA<L>(A, m0 + ml, k0 + k8 + i, sarg);
        }
#pragma unroll
        for (int i = 0; i < 8; i++) {
            int e = i * 256 + tid;
            int kl = e >> 7, nl = e & 127;
            Bs[kl][nl] = B[(k0 + kl) * NT + n0 + nl];
        }
        __syncthreads();
#pragma unroll
        for (int kk = 0; kk < 16; kk++) {
            float a[8], b[8];
#pragma unroll
            for (int i = 0; i < 8; i++) a[i] = As[kk][tr + i];
#pragma unroll
            for (int j = 0; j < 8; j++) b[j] = Bs[kk][tc + j];
#pragma unroll
            for (int i = 0; i < 8; i++)
#pragma unroll
                for (int j = 0; j < 8; j++)
                    acc[i][j] = fmaf(a[i], b[j], acc[i][j]);
        }
        __syncthreads();
    }

    // epilogue
#pragma unroll
    for (int i = 0; i < 8; i++) {
        int m = m0 + tr + i;
#pragma unroll
        for (int j = 0; j < 8; j++) {
            int col = n0 + tc + j;
            float v = acc[i][j];
            if constexpr (L == L_D3) {
                // scatter-add into y (N, o, t): col = o*4 + kk, t = 2s + kk
                C[m * 1280 + (col >> 2) * 10 + 2 * sarg + (col & 3)] += v;
            } else if constexpr (L == L_D4) {
                int n = m / 10, t = m - n * 10;
                C[n * 2560 + col * 10 + t] = v + bias[col];
            } else {
                v += bias[(L == L_D2) ? (col & 255) : col];
                if (RELU) v = fmaxf(v, 0.0f);
                C[m * NT + col] = v;
            }
        }
    }
}

// ---------------------------------------------------------------------------
// VQ: per-row argmin of d = fl( fl(|z|^2 + |e|^2) - 2 z.e )  — exact fp32
// replication of the reference's rounding so near-tie resolution matches.
// ---------------------------------------------------------------------------
__global__ __launch_bounds__(256, 2)
void vq_kernel()
{
    __shared__ float As[16][132];
    __shared__ float Bs[16][132];
    __shared__ float sd[128][17];
    __shared__ int   si[128][17];

    const int tid = threadIdx.x;
    const int m0 = blockIdx.x * 128;
    const int tr = (tid >> 4) * 8;
    const int tc = (tid & 15) * 8;

    float s1v[8];
#pragma unroll
    for (int i = 0; i < 8; i++) s1v[i] = g_zn[m0 + tr + i];

    float bestd[8];
    int   besti[8];
#pragma unroll
    for (int i = 0; i < 8; i++) { bestd[i] = 3.4e38f; besti[i] = 0; }

    for (int c0 = 0; c0 < 1024; c0 += 128) {
        float acc[8][8];
#pragma unroll
        for (int i = 0; i < 8; i++)
#pragma unroll
            for (int j = 0; j < 8; j++) acc[i][j] = 0.0f;

        for (int k0 = 0; k0 < 512; k0 += 16) {
            int ml = tid >> 1, k8 = (tid & 1) * 8;
#pragma unroll
            for (int i = 0; i < 8; i++)
                As[k8 + i][ml] = g_z[(m0 + ml) * 512 + k0 + k8 + i];
#pragma unroll
            for (int i = 0; i < 8; i++) {
                int e = i * 256 + tid;
                int kl = e >> 7, nl = e & 127;
                Bs[kl][nl] = g_CBt[(k0 + kl) * 1024 + c0 + nl];
            }
            __syncthreads();
#pragma unroll
            for (int kk = 0; kk < 16; kk++) {
                float a[8], b[8];
#pragma unroll
                for (int i = 0; i < 8; i++) a[i] = As[kk][tr + i];
#pragma unroll
                for (int j = 0; j < 8; j++) b[j] = Bs[kk][tc + j];
#pragma unroll
                for (int i = 0; i < 8; i++)
#pragma unroll
                    for (int j = 0; j < 8; j++)
                        acc[i][j] = fmaf(a[i], b[j], acc[i][j]);
            }
            __syncthreads();
        }
        // candidates (ascending code index => strict '<' keeps first min)
#pragma unroll
        for (int j = 0; j < 8; j++) {
            int code = c0 + tc + j;
            float cn = g_cbn[code];
#pragma unroll
            for (int i = 0; i < 8; i++) {
                // replicate: t = fl(s1 + s2); d = fl(t - 2p)  (2p exact; FMA = single round)
                float t = __fadd_rn(s1v[i], cn);
                float d = __fmaf_rn(-2.0f, acc[i][j], t);
                if (d < bestd[i]) { bestd[i] = d; besti[i] = code; }
            }
        }
    }

#pragma unroll
    for (int i = 0; i < 8; i++) { sd[tr + i][tid & 15] = bestd[i]; si[tr + i][tid & 15] = besti[i]; }
    __syncthreads();
    if (tid < 128) {
        float bd = sd[tid][0];
        int   bi = si[tid][0];
#pragma unroll
        for (int t = 1; t < 16; t++) {
            float d = sd[tid][t];
            int   ii = si[tid][t];
            if (d < bd || (d == bd && ii < bi)) { bd = d; bi = ii; }
        }
        g_idx[m0 + tid] = bi;
    }
}

// ---------------------------------------------------------------------------
// gather z_q_st = fl(z + fl(zq - z)) into output + accumulate ||z_q - z||^2
// ---------------------------------------------------------------------------
__global__ void gather_loss_kernel(const float* __restrict__ cb, float* __restrict__ zq_out)
{
    float lsum = 0.0f;
    for (int e = blockIdx.x * blockDim.x + threadIdx.x; e < NB * 512; e += gridDim.x * blockDim.x) {
        int n = e >> 9, k = e & 511;
        float zv = g_z[e];
        float cv = cb[g_idx[n] * 512 + k];
        float diff = __fadd_rn(cv, -zv);           // fl(zq - z)
        zq_out[e] = __fadd_rn(zv, diff);           // fl(z + fl(zq - z))  == z_q_st
        lsum = fmaf(diff, diff, lsum);
    }
    __shared__ float red[256];
    red[threadIdx.x] = lsum;
    __syncthreads();
    for (int s = 128; s > 0; s >>= 1) {
        if ((int)threadIdx.x < s) red[threadIdx.x] += red[threadIdx.x + s];
        __syncthreads();
    }
    if (threadIdx.x == 0) atomicAdd(&g_loss, (double)red[0]);
}

__global__ void yinit_kernel(const float* __restrict__ db3)
{
    for (int e = blockIdx.x * blockDim.x + threadIdx.x; e < NB * 1280; e += gridDim.x * blockDim.x) {
        int r = e % 1280;
        g_y[e] = db3[r / 10];
    }
}

__global__ void finalize_kernel(float* __restrict__ out)
{
    int n = blockIdx.x * blockDim.x + threadIdx.x;
    if (n < NB) out[IDX_OFF + n] = (float)g_idx[n];
    if (n == 0) {
        out[EMB_OFF]     = (float)(1.25 * (g_loss / 8388608.0));
        out[EMB_OFF + 1] = 0.0f;
        out[EMB_OFF + 2] = 0.0f;
    }
}

// ---------------------------------------------------------------------------
extern "C" void kernel_launch(void* const* d_in, const int* in_sizes, int n_in,
                              void* d_out, int out_size)
{
    (void)in_sizes; (void)n_in; (void)out_size;
    const float* x   = (const float*)d_in[0];
    const float* cb  = (const float*)d_in[1];
    const float* ew1 = (const float*)d_in[2];
    const float* eb1 = (const float*)d_in[3];
    const float* ew2 = (const float*)d_in[4];
    const float* eb2 = (const float*)d_in[5];
    const float* ew3 = (const float*)d_in[6];
    const float* eb3 = (const float*)d_in[7];
    const float* ew4 = (const float*)d_in[8];
    const float* eb4 = (const float*)d_in[9];
    const float* dw1 = (const float*)d_in[10];
    const float* db1 = (const float*)d_in[11];
    const float* dw2 = (const float*)d_in[12];
    const float* db2 = (const float*)d_in[13];
    const float* dw3 = (const float*)d_in[14];
    const float* db3 = (const float*)d_in[15];
    const float* dw4 = (const float*)d_in[16];
    const float* db4 = (const float*)d_in[17];
    float* out = (float*)d_out;

    prep_kernel<<<2048, 256>>>(ew1, ew2, ew3, ew4, cb, dw2);

    gemm_k<L_E1><<<dim3(1, 1280), 256>>>(x, nullptr, eb1, nullptr, 0);
    gemm_k<L_E2><<<dim3(2, 512),  256>>>(nullptr, nullptr, eb2, nullptr, 0);
    gemm_k<L_E3><<<dim3(4, 128),  256>>>(nullptr, nullptr, eb3, nullptr, 0);
    gemm_k<L_E4><<<dim3(4, 128),  256>>>(nullptr, nullptr, eb4, nullptr, 0);

    rownorm_kernel<<<NB / 8, 256>>>();
    vq_kernel<<<128, 256>>>();
    gather_loss_kernel<<<2048, 256>>>(cb, out + ZQ_OFF);
    finalize_kernel<<<64, 256>>>(out);

    gemm_k<L_D1><<<dim3(4, 128), 256>>>(out + ZQ_OFF, dw1, db1, nullptr, 0);
    gemm_k<L_D2><<<dim3(8, 128), 256>>>(nullptr, nullptr, db2, nullptr, 0);
    yinit_kernel<<<2048, 256>>>(db3);
    for (int s = 0; s < 4; s++)
        gemm_k<L_D3><<<dim3(4, 128), 256>>>(nullptr, dw3, nullptr, nullptr, s);
    gemm_k<L_D4><<<dim3(2, 1280), 256>>>(nullptr, dw4, db4, out + XHAT_OFF, 0);
}

// round 3
// speedup vs baseline: 1.1319x; 1.1319x over previous
#include <cuda_runtime.h>

#define NB 16384

enum { L_E1 = 0, L_E2, L_E3, L_E4, L_D1, L_D2, L_D3, L_D4 };

// Output layout (concatenated flat outputs, float32):
//   zq3   : [0, 8388608)            (N,512,1)
//   x_hat : [8388608, 50331648)     (N,256,10)
//   idx   : [50331648, 50348032)    (N,1) as float
//   emb_loss, qq_loss, ac_loss : 3 scalars
#define ZQ_OFF   0
#define XHAT_OFF 8388608
#define IDX_OFF  50331648
#define EMB_OFF  50348032

// ---- scratch (device globals; no allocation allowed) ----
__device__ float g_h1[NB * 1280];   // (N,10,128) encoder conv1 out (post-relu)
__device__ float g_h2[NB * 1024];   // (N,4,256)  encoder conv2 out (post-relu)
__device__ float g_h3[NB * 512];    // (N,512)    encoder conv3 out (post-relu)
__device__ float g_z [NB * 512];    // (N,512)    z_e
__device__ float g_zn[NB];          // |z|^2 per row, correctly-rounded fp32
__device__ float g_d1[NB * 512];    // (N,512)    decoder convT1 out (post-relu)
__device__ float g_d2[NB * 1024];   // (N, s(4), i(256)) decoder convT2 out (post-relu)
__device__ float g_y [NB * 1280];   // (N, o(128), t(10)) convT3 accumulator (pre-relu)
__device__ int   g_idx[NB];

// transformed weights: uniform [K][N] layout
__device__ float g_W1t[256 * 128];
__device__ float g_W2t[512 * 256];
__device__ float g_W3t[1024 * 512];
__device__ float g_W4t[512 * 512];
__device__ float g_V2t[512 * 1024];
__device__ float g_CBt[512 * 1024]; // codebook transposed (k, e)
__device__ float g_cbn[1024];       // |e|^2 (fp64-accumulated, rounded to fp32)
__device__ double g_loss;

// ---------------------------------------------------------------------------
// weight pre-transforms (cheap, a few MB, run every launch)
// ---------------------------------------------------------------------------
__global__ void prep_kernel(const float* __restrict__ ew1, const float* __restrict__ ew2,
                            const float* __restrict__ ew3, const float* __restrict__ ew4,
                            const float* __restrict__ cb,  const float* __restrict__ dw2)
{
    int e = blockIdx.x * blockDim.x + threadIdx.x;   // 524288 threads
    if (e < 256 * 128)  { int k = e >> 7,  o = e & 127;  g_W1t[e] = ew1[o * 256 + k]; }
    if (e < 512 * 256)  { int k = e >> 8,  o = e & 255;  g_W2t[e] = ew2[o * 512 + (k & 127) * 4 + (k >> 7)]; }
    if (e < 1024 * 512) { int k = e >> 9,  o = e & 511;  g_W3t[e] = ew3[o * 1024 + (k & 255) * 4 + (k >> 8)]; }
    if (e < 512 * 512)  { int k = e >> 9,  o = e & 511;  g_W4t[e] = ew4[o * 512 + k]; }
    if (e < 512 * 1024) { int k = e >> 10, c = e & 1023; g_CBt[e] = cb[c * 512 + k]; }
    if (e < 512 * 1024) { int k = e >> 10, j = e & 1023; g_V2t[e] = dw2[k * 1024 + (j & 255) * 4 + (j >> 8)]; }
    if (e < 1024) {
        // |e|^2: fp32 elementwise square (as the reference does), fp64 sum, round once.
        double s = 0.0;
        for (int k = 0; k < 512; k++) { float v = cb[e * 512 + k]; s += (double)(v * v); }
        g_cbn[e] = (float)s;
    }
    if (e == 0) g_loss = 0.0;
}

// ---------------------------------------------------------------------------
// per-row |z|^2: fp32 squares, fp64 accumulate, single rounding to fp32
// ---------------------------------------------------------------------------
__global__ void rownorm_kernel()
{
    int warp = (blockIdx.x * blockDim.x + threadIdx.x) >> 5;  // one warp per row
    int lane = threadIdx.x & 31;
    if (warp >= NB) return;
    const float* zr = g_z + warp * 512;
    double s = 0.0;
    for (int k = lane; k < 512; k += 32) {
        float v = zr[k];
        s += (double)(v * v);
    }
#pragma unroll
    for (int o = 16; o > 0; o >>= 1)
        s += __shfl_down_sync(0xffffffffu, s, o);
    if (lane == 0) g_zn[warp] = (float)s;
}

// ---------------------------------------------------------------------------
// per-layer A-tile element loads (im2col folded in)
// ---------------------------------------------------------------------------
template <int L>
__device__ __forceinline__ float ldA(const float* __restrict__ A, int m, int k, int sarg)
{
    if constexpr (L == L_E1) {           // x (N,256,10), m = n*10+t
        int n = m / 10, t = m - n * 10;
        return A[n * 2560 + k * 10 + t];
    } else if constexpr (L == L_E2) {    // h1 (N,10,128), m = n*4+s, k = kk*128+i
        int n = m >> 2, s = m & 3;
        return A[(n * 10 + 2 * s + (k >> 7)) * 128 + (k & 127)];
    } else if constexpr (L == L_E3) {
        return A[m * 1024 + k];
    } else if constexpr (L == L_D3) {    // d2 (N, s, i): slice sarg
        return A[m * 1024 + sarg * 256 + k];
    } else if constexpr (L == L_D4) {    // y (N,o,t) with deferred relu, m = n*10+t, k = o
        int n = m / 10, t = m - n * 10;
        return fmaxf(A[n * 1280 + k * 10 + t], 0.0f);
    } else {                             // E4, D1, D2: (N,512)
        return A[m * 512 + k];
    }
}

// ===========================================================================
// fp32 SGEMM core: 128x128 block, BK=8, 256 threads, split 2x2 of 4x4 frags,
// float4 smem fragments, register-prefetch double buffering.
// ===========================================================================
#define GEMM_CORE_DECLS                                                        \
    __shared__ float As[2][8][128];                                            \
    __shared__ float Bs[2][8][128];                                            \
    const int tid  = threadIdx.x;                                              \
    const int tr2  = (tid >> 4) * 4;                                           \
    const int tc2  = (tid & 15) * 4;                                           \
    const int ml   = tid & 127;                                                \
    const int kA   = tid >> 7;   /* 0/1 */                                     \
    const int brow = tid >> 5;   /* 0..7 */                                    \
    const int bcol = (tid & 31) * 4;

// one K-sweep of the FMA pipeline over [0,K) with A from ldA<L>, B row-major
template <int L, int K, int NT>
__device__ __forceinline__ void gemm_sweep(
    const float* __restrict__ A, const float* __restrict__ B,
    int m0, int n0, int sarg,
    float As[2][8][128], float Bs[2][8][128],
    int tid, int tr2, int tc2, int ml, int kA, int brow, int bcol,
    float acc[8][8])
{
    // prologue: tile 0 straight to smem buffer 0
#pragma unroll
    for (int i = 0; i < 4; i++)
        As[0][2 * i + kA][ml] = ldA<L>(A, m0 + ml, 2 * i + kA, sarg);
    *(float4*)&Bs[0][brow][bcol] = *(const float4*)&B[brow * NT + n0 + bcol];
    __syncthreads();

    int buf = 0;
#pragma unroll 1
    for (int k0 = 0; k0 < K; k0 += 8) {
        float  ar[4];
        float4 br;
        const bool more = (k0 + 8 < K);
        if (more) {
#pragma unroll
            for (int i = 0; i < 4; i++)
                ar[i] = ldA<L>(A, m0 + ml, k0 + 8 + 2 * i + kA, sarg);
            br = *(const float4*)&B[(k0 + 8 + brow) * NT + n0 + bcol];
        }
#pragma unroll
        for (int kk = 0; kk < 8; kk++) {
            float a[8], b[8];
            *(float4*)&a[0] = *(const float4*)&As[buf][kk][tr2];
            *(float4*)&a[4] = *(const float4*)&As[buf][kk][tr2 + 64];
            *(float4*)&b[0] = *(const float4*)&Bs[buf][kk][tc2];
            *(float4*)&b[4] = *(const float4*)&Bs[buf][kk][tc2 + 64];
#pragma unroll
            for (int ii = 0; ii < 8; ii++)
#pragma unroll
                for (int jj = 0; jj < 8; jj++)
                    acc[ii][jj] = fmaf(a[ii], b[jj], acc[ii][jj]);
        }
        if (more) {
#pragma unroll
            for (int i = 0; i < 4; i++)
                As[buf ^ 1][2 * i + kA][ml] = ar[i];
            *(float4*)&Bs[buf ^ 1][brow][bcol] = br;
            __syncthreads();
            buf ^= 1;
        }
    }
}

// ---------------------------------------------------------------------------
// generic fp32 SGEMM with per-layer epilogue
// ---------------------------------------------------------------------------
template <int L>
__global__ __launch_bounds__(256, 2)
void gemm_k(const float* __restrict__ extA, const float* __restrict__ extB,
            const float* __restrict__ bias, float* __restrict__ extC, int sarg)
{
    constexpr int K  = (L == L_E1) ? 256 : (L == L_E2) ? 512 : (L == L_E3) ? 1024 :
                       (L == L_E4) ? 512 : (L == L_D1) ? 512 : (L == L_D2) ? 512 :
                       (L == L_D3) ? 256 : 128;
    constexpr int NT = (L == L_E1) ? 128 : (L == L_E2) ? 256 : (L == L_E3) ? 512 :
                       (L == L_E4) ? 512 : (L == L_D1) ? 512 : (L == L_D2) ? 1024 :
                       (L == L_D3) ? 512 : 256;
    constexpr bool RELU = (L == L_E1 || L == L_E2 || L == L_E3 || L == L_D1 || L == L_D2);

    const float* A = extA;
    const float* B = extB;
    float* C = extC;
    if constexpr (L == L_E1) { B = g_W1t; C = g_h1; }
    if constexpr (L == L_E2) { A = g_h1; B = g_W2t; C = g_h2; }
    if constexpr (L == L_E3) { A = g_h2; B = g_W3t; C = g_h3; }
    if constexpr (L == L_E4) { A = g_h3; B = g_W4t; C = g_z; }
    if constexpr (L == L_D1) { C = g_d1; }
    if constexpr (L == L_D2) { A = g_d1; B = g_V2t; C = g_d2; }
    if constexpr (L == L_D3) { A = g_d2; C = g_y; }
    if constexpr (L == L_D4) { A = g_y; }

    GEMM_CORE_DECLS
    const int m0 = blockIdx.y * 128;
    const int n0 = blockIdx.x * 128;

    float acc[8][8];
#pragma unroll
    for (int i = 0; i < 8; i++)
#pragma unroll
        for (int j = 0; j < 8; j++) acc[i][j] = 0.0f;

    gemm_sweep<L, K, NT>(A, B, m0, n0, sarg, As, Bs, tid, tr2, tc2, ml, kA, brow, bcol, acc);

    // epilogue
#pragma unroll
    for (int ii = 0; ii < 8; ii++) {
        const int m = m0 + tr2 + (ii & 3) + ((ii & 4) ? 64 : 0);
#pragma unroll
        for (int jj = 0; jj < 8; jj++) {
            const int col = n0 + tc2 + (jj & 3) + ((jj & 4) ? 64 : 0);
            float v = acc[ii][jj];
            if constexpr (L == L_D3) {
                // scatter-add into y (N, o, t): col = o*4 + kk, t = 2s + kk
                C[m * 1280 + (col >> 2) * 10 + 2 * sarg + (col & 3)] += v;
            } else if constexpr (L == L_D4) {
                int n = m / 10, t = m - n * 10;
                C[n * 2560 + col * 10 + t] = v + bias[col];
            } else {
                v += bias[(L == L_D2) ? (col & 255) : col];
                if (RELU) v = fmaxf(v, 0.0f);
                C[m * NT + col] = v;
            }
        }
    }
}

// ---------------------------------------------------------------------------
// VQ: per-row argmin of d = fl( fl(|z|^2 + |e|^2) - 2 z.e )  — exact fp32
// replication of the reference's rounding so near-tie resolution matches.
// ---------------------------------------------------------------------------
__global__ __launch_bounds__(256, 2)
void vq_kernel()
{
    GEMM_CORE_DECLS
    __shared__ float sd[128][16];
    __shared__ int   si[128][16];

    const int m0 = blockIdx.x * 128;

    float s1v[8];
#pragma unroll
    for (int ii = 0; ii < 8; ii++)
        s1v[ii] = g_zn[m0 + tr2 + (ii & 3) + ((ii & 4) ? 64 : 0)];

    float bestd[8];
    int   besti[8];
#pragma unroll
    for (int i = 0; i < 8; i++) { bestd[i] = 3.4e38f; besti[i] = 0; }

#pragma unroll 1
    for (int c0 = 0; c0 < 1024; c0 += 128) {
        float acc[8][8];
#pragma unroll
        for (int i = 0; i < 8; i++)
#pragma unroll
            for (int j = 0; j < 8; j++) acc[i][j] = 0.0f;

        gemm_sweep<L_E4, 512, 1024>(g_z, g_CBt, m0, c0, 0,
                                    As, Bs, tid, tr2, tc2, ml, kA, brow, bcol, acc);
        __syncthreads();   // safe reuse of As/Bs next c0 iteration

        // candidates (ascending code order within thread => strict '<' keeps first min)
#pragma unroll
        for (int jj = 0; jj < 8; jj++) {
            const int code = c0 + tc2 + (jj & 3) + ((jj & 4) ? 64 : 0);
            const float cn = g_cbn[code];
#pragma unroll
            for (int ii = 0; ii < 8; ii++) {
                // replicate: t = fl(s1 + s2); d = fl(t - 2p)  (2p exact; FMA = single round)
                float t = __fadd_rn(s1v[ii], cn);
                float d = __fmaf_rn(-2.0f, acc[ii][jj], t);
                if (d < bestd[ii]) { bestd[ii] = d; besti[ii] = code; }
            }
        }
    }

#pragma unroll
    for (int ii = 0; ii < 8; ii++) {
        const int r = tr2 + (ii & 3) + ((ii & 4) ? 64 : 0);
        sd[r][tid & 15] = bestd[ii];
        si[r][tid & 15] = besti[ii];
    }
    __syncthreads();
    if (tid < 128) {
        float bd = sd[tid][0];
        int   bi = si[tid][0];
#pragma unroll
        for (int t = 1; t < 16; t++) {
            float d = sd[tid][t];
            int   ii = si[tid][t];
            if (d < bd || (d == bd && ii < bi)) { bd = d; bi = ii; }
        }
        g_idx[m0 + tid] = bi;
    }
}

// ---------------------------------------------------------------------------
// gather z_q_st = fl(z + fl(zq - z)) into output + accumulate ||z_q - z||^2
// ---------------------------------------------------------------------------
__global__ void gather_loss_kernel(const float* __restrict__ cb, float* __restrict__ zq_out)
{
    float lsum = 0.0f;
    for (int e = blockIdx.x * blockDim.x + threadIdx.x; e < NB * 512; e += gridDim.x * blockDim.x) {
        int n = e >> 9, k = e & 511;
        float zv = g_z[e];
        float cv = cb[g_idx[n] * 512 + k];
        float diff = __fadd_rn(cv, -zv);           // fl(zq - z)
        zq_out[e] = __fadd_rn(zv, diff);           // fl(z + fl(zq - z))  == z_q_st
        lsum = fmaf(diff, diff, lsum);
    }
    __shared__ float red[256];
    red[threadIdx.x] = lsum;
    __syncthreads();
    for (int s = 128; s > 0; s >>= 1) {
        if ((int)threadIdx.x < s) red[threadIdx.x] += red[threadIdx.x + s];
        __syncthreads();
    }
    if (threadIdx.x == 0) atomicAdd(&g_loss, (double)red[0]);
}

__global__ void yinit_kernel(const float* __restrict__ db3)
{
    for (int e = blockIdx.x * blockDim.x + threadIdx.x; e < NB * 1280; e += gridDim.x * blockDim.x) {
        int r = e % 1280;
        g_y[e] = db3[r / 10];
    }
}

__global__ void finalize_kernel(float* __restrict__ out)
{
    int n = blockIdx.x * blockDim.x + threadIdx.x;
    if (n < NB) out[IDX_OFF + n] = (float)g_idx[n];
    if (n == 0) {
        out[EMB_OFF]     = (float)(1.25 * (g_loss / 8388608.0));
        out[EMB_OFF + 1] = 0.0f;
        out[EMB_OFF + 2] = 0.0f;
    }
}

// ---------------------------------------------------------------------------
extern "C" void kernel_launch(void* const* d_in, const int* in_sizes, int n_in,
                              void* d_out, int out_size)
{
    (void)in_sizes; (void)n_in; (void)out_size;
    const float* x   = (const float*)d_in[0];
    const float* cb  = (const float*)d_in[1];
    const float* ew1 = (const float*)d_in[2];
    const float* eb1 = (const float*)d_in[3];
    const float* ew2 = (const float*)d_in[4];
    const float* eb2 = (const float*)d_in[5];
    const float* ew3 = (const float*)d_in[6];
    const float* eb3 = (const float*)d_in[7];
    const float* ew4 = (const float*)d_in[8];
    const float* eb4 = (const float*)d_in[9];
    const float* dw1 = (const float*)d_in[10];
    const float* db1 = (const float*)d_in[11];
    const float* dw2 = (const float*)d_in[12];
    const float* db2 = (const float*)d_in[13];
    const float* dw3 = (const float*)d_in[14];
    const float* db3 = (const float*)d_in[15];
    const float* dw4 = (const float*)d_in[16];
    const float* db4 = (const float*)d_in[17];
    float* out = (float*)d_out;

    prep_kernel<<<2048, 256>>>(ew1, ew2, ew3, ew4, cb, dw2);

    gemm_k<L_E1><<<dim3(1, 1280), 256>>>(x, nullptr, eb1, nullptr, 0);
    gemm_k<L_E2><<<dim3(2, 512),  256>>>(nullptr, nullptr, eb2, nullptr, 0);
    gemm_k<L_E3><<<dim3(4, 128),  256>>>(nullptr, nullptr, eb3, nullptr, 0);
    gemm_k<L_E4><<<dim3(4, 128),  256>>>(nullptr, nullptr, eb4, nullptr, 0);

    rownorm_kernel<<<NB / 8, 256>>>();
    vq_kernel<<<128, 256>>>();
    gather_loss_kernel<<<2048, 256>>>(cb, out + ZQ_OFF);
    finalize_kernel<<<64, 256>>>(out);

    gemm_k<L_D1><<<dim3(4, 128), 256>>>(out + ZQ_OFF, dw1, db1, nullptr, 0);
    gemm_k<L_D2><<<dim3(8, 128), 256>>>(nullptr, nullptr, db2, nullptr, 0);
    yinit_kernel<<<2048, 256>>>(db3);
    for (int s = 0; s < 4; s++)
        gemm_k<L_D3><<<dim3(4, 128), 256>>>(nullptr, dw3, nullptr, nullptr, s);
    gemm_k<L_D4><<<dim3(2, 1280), 256>>>(nullptr, dw4, db4, out + XHAT_OFF, 0);
}